// round 5
// baseline (speedup 1.0000x reference)
#include <cuda_runtime.h>
#include <math.h>

// Problem constants (fixed by setup_inputs)
#define B_      2
#define L_      4096
#define H_      16
#define P_      128
#define NSTATE  256
#define CH      256
#define NC      16        // L_/CH
#define S_      4         // 2*B_ (fw + bw sequences)
#define DIN     2048      // H_*P_
#define DT_COLS 32        // 2*H_

// ---------------- scratch (device globals: allocation-free) ----------------
__device__ float g_ei [S_*NC*H_*CH];            // exp(cs)            [sjh][i]
__device__ float g_ekd[S_*NC*H_*CH];            // exp(-cs)*dt        [sjh][k]
__device__ float g_cd [S_*NC*H_];               // exp(cs_last)       [sjh]
__device__ float g_CBT[S_*NC*CH*CH];            // (C B^T)^T          [sj][k][i]
__device__ float g_states[S_*NC*H_*NSTATE*P_];  // chunk states / prev (134 MB)
__device__ float g_ysc[S_*L_*H_*P_];            // raw scan output     (134 MB)

// ---------------- kernel 1: softplus + per-chunk cumsum --------------------
// grid: S_*NC blocks, 512 threads (warp w = head w)
__global__ void k_prep(const float* __restrict__ dt, const float* __restrict__ A_log)
{
    int sj = blockIdx.x;
    int s = sj >> 4, j = sj & 15;
    int w = threadIdx.x >> 5, lane = threadIdx.x & 31;

    float A = -expf(A_log[w]);
    bool fwd = (s < B_);
    int bb   = fwd ? s : s - B_;
    int hcol = fwd ? w : (H_ + w);
    int base = (sj * H_ + w) * CH;

    float carry = 0.f;
    #pragma unroll
    for (int it = 0; it < CH / 32; ++it) {
        int i = it * 32 + lane;
        int t = j * CH + i;
        int tg = fwd ? t : (L_ - 1 - t);
        float draw = dt[(bb * L_ + tg) * DT_COLS + hcol];
        float dsp  = (draw > 20.f) ? draw : log1pf(expf(draw));
        float v = dsp * A;

        float sc = v;                       // inclusive warp scan
        #pragma unroll
        for (int off = 1; off < 32; off <<= 1) {
            float y = __shfl_up_sync(0xffffffffu, sc, off);
            if (lane >= off) sc += y;
        }
        float cs = sc + carry;
        g_ei [base + i] = expf(cs);
        g_ekd[base + i] = expf(-cs) * dsp;
        if (i == CH - 1) g_cd[sj * H_ + w] = expf(cs);
        carry = __shfl_sync(0xffffffffu, cs, 31);
    }
}

// ---------------- kernel 2: CBT[k][i] = sum_n B[k,n] * C[i,n] ---------------
// grid: (8, S_*NC); block 256; 64(k) x 128(i) tile, K=256
__global__ __launch_bounds__(256) void k_cb(const float* __restrict__ BC)
{
    int sj = blockIdx.y;
    int s = sj >> 4, j = sj & 15;
    int kt = blockIdx.x & 3, it = blockIdx.x >> 2;
    int k0 = kt * 64, i0 = it * 128;
    bool fwd = (s < B_);
    int bb = fwd ? s : s - B_;
    int tid = threadIdx.x, ty = tid >> 4, tx = tid & 15;

    __shared__ __align__(16) float As[16 * 68];   // [n][k] 16x64
    __shared__ __align__(16) float Cs[16 * 132];  // [n][i] 16x128

    float acc[4][8];
    #pragma unroll
    for (int u = 0; u < 4; u++)
        #pragma unroll
        for (int v = 0; v < 8; v++) acc[u][v] = 0.f;

    for (int n0 = 0; n0 < NSTATE; n0 += 16) {
        #pragma unroll
        for (int r = 0; r < 4; r++) {
            int e = tid + r * 256;
            int kl = e >> 4, nl = e & 15;
            int t = j * CH + k0 + kl;
            int tg = fwd ? t : (L_ - 1 - t);
            As[nl * 68 + kl] = BC[(bb * L_ + tg) * (2 * NSTATE) + n0 + nl];
        }
        #pragma unroll
        for (int r = 0; r < 8; r++) {
            int e = tid + r * 256;
            int il = e >> 4, nl = e & 15;
            int t = j * CH + i0 + il;
            int tg = fwd ? t : (L_ - 1 - t);
            Cs[nl * 132 + il] = BC[(bb * L_ + tg) * (2 * NSTATE) + NSTATE + n0 + nl];
        }
        __syncthreads();
        #pragma unroll
        for (int nn = 0; nn < 16; nn++) {
            float4 a  = *(const float4*)&As[nn * 68 + ty * 4];
            float4 b0 = *(const float4*)&Cs[nn * 132 + tx * 4];
            float4 b1 = *(const float4*)&Cs[nn * 132 + 64 + tx * 4];
            float av[4] = {a.x, a.y, a.z, a.w};
            float bv[8] = {b0.x, b0.y, b0.z, b0.w, b1.x, b1.y, b1.z, b1.w};
            #pragma unroll
            for (int u = 0; u < 4; u++)
                #pragma unroll
                for (int v = 0; v < 8; v++) acc[u][v] += av[u] * bv[v];
        }
        __syncthreads();
    }
    #pragma unroll
    for (int u = 0; u < 4; u++) {
        int k = k0 + ty * 4 + u;
        float* dst = &g_CBT[(sj * CH + k) * CH + i0];
        *(float4*)&dst[tx * 4]      = make_float4(acc[u][0], acc[u][1], acc[u][2], acc[u][3]);
        *(float4*)&dst[64 + tx * 4] = make_float4(acc[u][4], acc[u][5], acc[u][6], acc[u][7]);
    }
}

// ---------------- kernel 3: chunk states -----------------------------------
// states[n,p] = sum_k (cd*ekd[k]) * B[k,n] * x[k,h,p]
// grid: (4, S_*NC*H_); block 256; 64(n) x 128(p) tile, K=256
__global__ __launch_bounds__(256) void k_states(const float* __restrict__ x,
                                                const float* __restrict__ BC)
{
    int by = blockIdx.y;                 // sjh
    int s = by >> 8, j = (by >> 4) & 15, h = by & 15;
    int n0 = blockIdx.x * 64;
    bool fwd = (s < B_);
    int bb = fwd ? s : s - B_;
    int tid = threadIdx.x, ty = tid >> 4, tx = tid & 15;
    float cdv = g_cd[by];
    int ekb = by * CH;

    __shared__ __align__(16) float As[16 * 68];   // [k][n] 16x64 (weighted B)
    __shared__ __align__(16) float Xs[16 * 128];  // [k][p]

    float acc[4][8];
    #pragma unroll
    for (int u = 0; u < 4; u++)
        #pragma unroll
        for (int v = 0; v < 8; v++) acc[u][v] = 0.f;

    for (int k0 = 0; k0 < CH; k0 += 16) {
        #pragma unroll
        for (int r = 0; r < 4; r++) {
            int e = tid + r * 256;
            int kq = e >> 6, nn = e & 63;
            int t = j * CH + k0 + kq;
            int tg = fwd ? t : (L_ - 1 - t);
            float wgt = cdv * g_ekd[ekb + k0 + kq];
            As[kq * 68 + nn] = BC[(bb * L_ + tg) * (2 * NSTATE) + n0 + nn] * wgt;
        }
        #pragma unroll
        for (int r = 0; r < 8; r++) {
            int e = tid + r * 256;
            int kq = e >> 7, pp = e & 127;
            int t = j * CH + k0 + kq;
            int tg = fwd ? t : (L_ - 1 - t);
            Xs[kq * 128 + pp] = x[(bb * L_ + tg) * DIN + h * P_ + pp];
        }
        __syncthreads();
        #pragma unroll
        for (int kq = 0; kq < 16; kq++) {
            float4 a  = *(const float4*)&As[kq * 68 + ty * 4];
            float4 b0 = *(const float4*)&Xs[kq * 128 + tx * 4];
            float4 b1 = *(const float4*)&Xs[kq * 128 + 64 + tx * 4];
            float av[4] = {a.x, a.y, a.z, a.w};
            float bv[8] = {b0.x, b0.y, b0.z, b0.w, b1.x, b1.y, b1.z, b1.w};
            #pragma unroll
            for (int u = 0; u < 4; u++)
                #pragma unroll
                for (int v = 0; v < 8; v++) acc[u][v] += av[u] * bv[v];
        }
        __syncthreads();
    }
    #pragma unroll
    for (int u = 0; u < 4; u++) {
        int n = n0 + ty * 4 + u;
        float* dst = &g_states[(by * NSTATE + n) * P_];
        *(float4*)&dst[tx * 4]      = make_float4(acc[u][0], acc[u][1], acc[u][2], acc[u][3]);
        *(float4*)&dst[64 + tx * 4] = make_float4(acc[u][4], acc[u][5], acc[u][6], acc[u][7]);
    }
}

// ---------------- kernel 3b: inter-chunk recurrence (in place -> prev) -----
// grid: 8192 blocks x 256
__global__ void k_scan()
{
    int tid = blockIdx.x * 256 + threadIdx.x;
    int pv = tid & 127;
    int nv = (tid >> 7) & 255;
    int hh = (tid >> 15) & 15;
    int s  = tid >> 19;
    float carry = 0.f;
    #pragma unroll
    for (int j = 0; j < NC; ++j) {
        int sjh = (s * 16 + j) * 16 + hh;
        int idx = (sjh * NSTATE + nv) * P_ + pv;
        float st = g_states[idx];
        float d  = g_cd[sjh];
        g_states[idx] = carry;      // prev (state before this chunk)
        carry = carry * d + st;
    }
}

// ---------------- kernel 4: y = [G | ei*C] @ [X ; prev] --------------------
// G[i,k] = CBT[k][i]*ei[i]*ekd[k]*(k<=i); grid (2, S_*NC*H_); 128x128, K=512
__global__ __launch_bounds__(256) void k_y(const float* __restrict__ x,
                                           const float* __restrict__ BC)
{
    int by = blockIdx.y;                 // sjh
    int s = by >> 8, j = (by >> 4) & 15, h = by & 15;
    int sj = by >> 4;
    int i0 = blockIdx.x * 128;
    bool fwd = (s < B_);
    int bb = fwd ? s : s - B_;
    int tid = threadIdx.x, ty = tid >> 4, tx = tid & 15;
    int base = by * CH;

    __shared__ __align__(16) float As[16 * 132];
    __shared__ __align__(16) float Bs[16 * 128];
    __shared__ float eis[128];
    if (tid < 128) eis[tid] = g_ei[base + i0 + tid];
    __syncthreads();

    float acc[8][8];
    #pragma unroll
    for (int u = 0; u < 8; u++)
        #pragma unroll
        for (int v = 0; v < 8; v++) acc[u][v] = 0.f;

    int ntri = (i0 == 0) ? 8 : 16;       // skip fully-masked triangular tiles
    for (int kt = 0; kt < ntri + 16; ++kt) {
        bool first = (kt < ntri);
        int k0 = first ? kt * 16 : (kt - ntri) * 16;
        if (first) {
            #pragma unroll
            for (int r = 0; r < 8; r++) {
                int e = tid + r * 256;
                int kk = e >> 7, ii = e & 127;
                int kg = k0 + kk, ig = i0 + ii;
                float v = g_CBT[(sj * CH + kg) * CH + ig] * eis[ii] * g_ekd[base + kg];
                As[kk * 132 + ii] = (kg <= ig) ? v : 0.f;
            }
            #pragma unroll
            for (int r = 0; r < 8; r++) {
                int e = tid + r * 256;
                int kk = e >> 7, pp = e & 127;
                int t = j * CH + k0 + kk;
                int tg = fwd ? t : (L_ - 1 - t);
                Bs[kk * 128 + pp] = x[(bb * L_ + tg) * DIN + h * P_ + pp];
            }
        } else {
            #pragma unroll
            for (int r = 0; r < 8; r++) {
                int e = tid + r * 256;
                int ii = e >> 4, nl = e & 15;
                int ig = i0 + ii;
                int t = j * CH + ig;
                int tg = fwd ? t : (L_ - 1 - t);
                As[nl * 132 + ii] =
                    BC[(bb * L_ + tg) * (2 * NSTATE) + NSTATE + k0 + nl] * eis[ii];
            }
            #pragma unroll
            for (int r = 0; r < 8; r++) {
                int e = tid + r * 256;
                int kk = e >> 7, pp = e & 127;
                Bs[kk * 128 + pp] = g_states[(by * NSTATE + k0 + kk) * P_ + pp];
            }
        }
        __syncthreads();
        #pragma unroll
        for (int kk = 0; kk < 16; kk++) {
            float4 a0 = *(const float4*)&As[kk * 132 + ty * 4];
            float4 a1 = *(const float4*)&As[kk * 132 + 64 + ty * 4];
            float4 b0 = *(const float4*)&Bs[kk * 128 + tx * 4];
            float4 b1 = *(const float4*)&Bs[kk * 128 + 64 + tx * 4];
            float av[8] = {a0.x, a0.y, a0.z, a0.w, a1.x, a1.y, a1.z, a1.w};
            float bv[8] = {b0.x, b0.y, b0.z, b0.w, b1.x, b1.y, b1.z, b1.w};
            #pragma unroll
            for (int u = 0; u < 8; u++)
                #pragma unroll
                for (int v = 0; v < 8; v++) acc[u][v] += av[u] * bv[v];
        }
        __syncthreads();
    }
    #pragma unroll
    for (int u = 0; u < 8; u++) {
        int il = (u < 4) ? (ty * 4 + u) : (64 + ty * 4 + (u - 4));
        int t = j * CH + i0 + il;
        float* dst = &g_ysc[(s * L_ + t) * DIN + h * P_];
        *(float4*)&dst[tx * 4]      = make_float4(acc[u][0], acc[u][1], acc[u][2], acc[u][3]);
        *(float4*)&dst[64 + tx * 4] = make_float4(acc[u][4], acc[u][5], acc[u][6], acc[u][7]);
    }
}

// ---------------- kernel 5: gate + roll + flip fusion ----------------------
// out[bb,t] = ysc_fw[bb,t-1] + ysc_bw[B_+bb,L-2-t] + x*(x@W^T + D)
__global__ void k_fuse(const float* __restrict__ x, const float* __restrict__ W,
                       const float* __restrict__ D, float* __restrict__ out)
{
    int bt = blockIdx.x;
    int bb = bt / L_, t = bt % L_;
    __shared__ __align__(16) float xs[DIN];
    __shared__ float gate[H_];
    int tid = threadIdx.x;
    const float* xrow = x + (size_t)bt * DIN;
    #pragma unroll
    for (int r = 0; r < 2; r++) {
        int i4 = tid + r * 256;
        ((float4*)xs)[i4] = ((const float4*)xrow)[i4];
    }
    __syncthreads();

    int w = tid >> 5, lane = tid & 31;
    #pragma unroll
    for (int hh = w; hh < H_; hh += 8) {
        float g = 0.f;
        const float4* Wr = (const float4*)(W + hh * DIN);
        #pragma unroll
        for (int d4 = lane; d4 < DIN / 4; d4 += 32) {
            float4 xv = ((float4*)xs)[d4];
            float4 wv = Wr[d4];
            g += xv.x * wv.x + xv.y * wv.y + xv.z * wv.z + xv.w * wv.w;
        }
        #pragma unroll
        for (int off = 16; off; off >>= 1) g += __shfl_down_sync(0xffffffffu, g, off);
        if (lane == 0) gate[hh] = g + D[hh];
    }
    __syncthreads();

    const float4* yfw = (t > 0)
        ? (const float4*)(g_ysc + ((size_t)bb * L_ + (t - 1)) * DIN) : (const float4*)0;
    const float4* ybw = (t < L_ - 1)
        ? (const float4*)(g_ysc + ((size_t)(B_ + bb) * L_ + (L_ - 2 - t)) * DIN) : (const float4*)0;
    float4* o = (float4*)(out + (size_t)bt * DIN);
    #pragma unroll
    for (int r = 0; r < 2; r++) {
        int i4 = tid + r * 256;
        float4 xv = ((float4*)xs)[i4];
        float gh = gate[i4 >> 5];
        float4 a = yfw ? yfw[i4] : make_float4(0.f, 0.f, 0.f, 0.f);
        float4 b = ybw ? ybw[i4] : make_float4(0.f, 0.f, 0.f, 0.f);
        float4 res;
        res.x = a.x + b.x + xv.x * gh;
        res.y = a.y + b.y + xv.y * gh;
        res.z = a.z + b.z + xv.z * gh;
        res.w = a.w + b.w + xv.w * gh;
        o[i4] = res;
    }
}

// ---------------- launcher --------------------------------------------------
extern "C" void kernel_launch(void* const* d_in, const int* in_sizes, int n_in,
                              void* d_out, int out_size)
{
    (void)in_sizes; (void)n_in; (void)out_size;
    const float* x     = (const float*)d_in[0];
    const float* BC    = (const float*)d_in[1];
    const float* dt    = (const float*)d_in[2];
    const float* A_log = (const float*)d_in[3];
    const float* D     = (const float*)d_in[4];
    const float* W     = (const float*)d_in[5];
    float* out = (float*)d_out;

    k_prep  <<<S_ * NC, 512>>>(dt, A_log);
    k_cb    <<<dim3(8, S_ * NC), 256>>>(BC);
    k_states<<<dim3(4, S_ * NC * H_), 256>>>(x, BC);
    k_scan  <<<(S_ * H_ * NSTATE * P_) / 256, 256>>>();
    k_y     <<<dim3(2, S_ * NC * H_), 256>>>(x, BC);
    k_fuse  <<<B_ * L_, 256>>>(x, W, D, out);
}

// round 7
// speedup vs baseline: 2.1879x; 2.1879x over previous
#include <cuda_runtime.h>
#include <math.h>

// Problem constants (fixed by setup_inputs)
#define B_      2
#define L_      4096
#define H_      16
#define P_      128
#define NSTATE  256
#define CH      256
#define NC      16        // L_/CH
#define S_      4         // 2*B_ (fw + bw sequences)
#define DIN     2048      // H_*P_
#define DT_COLS 32        // 2*H_
#define PITCH   136       // smem pitch: conflict-free tf32 fragment loads

// ---------------- scratch (device globals: allocation-free) ----------------
__device__ float g_ei [S_*NC*H_*CH];            // exp(cs)            [sjh][i]
__device__ float g_ekd[S_*NC*H_*CH];            // exp(-cs)*dt        [sjh][k]
__device__ float g_cd [S_*NC*H_];               // exp(cs_last)       [sjh]
__device__ float g_CBT[S_*NC*CH*CH];            // (C B^T)^T          [sj][k][i]
__device__ float g_states[S_*NC*H_*NSTATE*P_];  // chunk states / prev (134 MB)
__device__ float g_ysc[S_*L_*H_*P_];            // raw scan output     (134 MB)

// ---------------- tf32 helpers ----------------------------------------------
__device__ __forceinline__ float f2tf(float x) {
    unsigned u;
    asm("cvt.rna.tf32.f32 %0, %1;" : "=r"(u) : "f"(x));
    return __uint_as_float(u);
}

__device__ __forceinline__ void mma_tf32(float d[4], const unsigned a[4], const unsigned b[2]) {
    asm volatile(
        "mma.sync.aligned.m16n8k8.row.col.f32.tf32.tf32.f32 "
        "{%0,%1,%2,%3}, {%4,%5,%6,%7}, {%8,%9}, {%0,%1,%2,%3};"
        : "+f"(d[0]), "+f"(d[1]), "+f"(d[2]), "+f"(d[3])
        : "r"(a[0]), "r"(a[1]), "r"(a[2]), "r"(a[3]), "r"(b[0]), "r"(b[1]));
}

// One K=16 step. As/Bs: [16][PITCH] in (k x m)/(k x n) layout, tf32 values.
// Warp (wr,wc) computes rows [wr*32, wr*32+32) x cols [wc*64, wc*64+64).
__device__ __forceinline__ void mma_step16(const float* __restrict__ As,
                                           const float* __restrict__ Bs,
                                           float acc[2][8][4], int wr, int wc, int lane)
{
    int g = lane >> 2, tig = lane & 3;
    #pragma unroll
    for (int kk = 0; kk < 16; kk += 8) {
        unsigned a[2][4], b[8][2];
        #pragma unroll
        for (int mt = 0; mt < 2; mt++) {
            int mb = wr * 32 + mt * 16;
            a[mt][0] = __float_as_uint(As[(kk + tig)     * PITCH + mb + g]);
            a[mt][1] = __float_as_uint(As[(kk + tig)     * PITCH + mb + g + 8]);
            a[mt][2] = __float_as_uint(As[(kk + tig + 4) * PITCH + mb + g]);
            a[mt][3] = __float_as_uint(As[(kk + tig + 4) * PITCH + mb + g + 8]);
        }
        #pragma unroll
        for (int nt = 0; nt < 8; nt++) {
            int nb = wc * 64 + nt * 8;
            b[nt][0] = __float_as_uint(Bs[(kk + tig)     * PITCH + nb + g]);
            b[nt][1] = __float_as_uint(Bs[(kk + tig + 4) * PITCH + nb + g]);
        }
        #pragma unroll
        for (int mt = 0; mt < 2; mt++)
            #pragma unroll
            for (int nt = 0; nt < 8; nt++)
                mma_tf32(acc[mt][nt], a[mt], b[nt]);
    }
}

// ---------------- kernel 1: softplus + per-chunk cumsum --------------------
__global__ void k_prep(const float* __restrict__ dt, const float* __restrict__ A_log)
{
    int sj = blockIdx.x;
    int s = sj >> 4, j = sj & 15;
    int w = threadIdx.x >> 5, lane = threadIdx.x & 31;

    float A = -expf(A_log[w]);
    bool fwd = (s < B_);
    int bb   = fwd ? s : s - B_;
    int hcol = fwd ? w : (H_ + w);
    int base = (sj * H_ + w) * CH;

    float carry = 0.f;
    #pragma unroll
    for (int it = 0; it < CH / 32; ++it) {
        int i = it * 32 + lane;
        int t = j * CH + i;
        int tg = fwd ? t : (L_ - 1 - t);
        float draw = dt[(bb * L_ + tg) * DT_COLS + hcol];
        float dsp  = (draw > 20.f) ? draw : log1pf(expf(draw));
        float v = dsp * A;

        float sc = v;
        #pragma unroll
        for (int off = 1; off < 32; off <<= 1) {
            float y = __shfl_up_sync(0xffffffffu, sc, off);
            if (lane >= off) sc += y;
        }
        float cs = sc + carry;
        g_ei [base + i] = expf(cs);
        g_ekd[base + i] = expf(-cs) * dsp;
        if (i == CH - 1) g_cd[sj * H_ + w] = expf(cs);
        carry = __shfl_sync(0xffffffffu, cs, 31);
    }
}

// ---------------- kernel 2: CBT[k][i] = sum_n B[k,n] * C[i,n] (SIMT) --------
__global__ __launch_bounds__(256) void k_cb(const float* __restrict__ BC)
{
    int sj = blockIdx.y;
    int s = sj >> 4, j = sj & 15;
    int kt = blockIdx.x & 3, it = blockIdx.x >> 2;
    int k0 = kt * 64, i0 = it * 128;
    bool fwd = (s < B_);
    int bb = fwd ? s : s - B_;
    int tid = threadIdx.x, ty = tid >> 4, tx = tid & 15;

    __shared__ __align__(16) float As[16 * 68];
    __shared__ __align__(16) float Cs[16 * 132];

    float acc[4][8];
    #pragma unroll
    for (int u = 0; u < 4; u++)
        #pragma unroll
        for (int v = 0; v < 8; v++) acc[u][v] = 0.f;

    for (int n0 = 0; n0 < NSTATE; n0 += 16) {
        #pragma unroll
        for (int r = 0; r < 4; r++) {
            int e = tid + r * 256;
            int kl = e >> 4, nl = e & 15;
            int t = j * CH + k0 + kl;
            int tg = fwd ? t : (L_ - 1 - t);
            As[nl * 68 + kl] = BC[(bb * L_ + tg) * (2 * NSTATE) + n0 + nl];
        }
        #pragma unroll
        for (int r = 0; r < 8; r++) {
            int e = tid + r * 256;
            int il = e >> 4, nl = e & 15;
            int t = j * CH + i0 + il;
            int tg = fwd ? t : (L_ - 1 - t);
            Cs[nl * 132 + il] = BC[(bb * L_ + tg) * (2 * NSTATE) + NSTATE + n0 + nl];
        }
        __syncthreads();
        #pragma unroll
        for (int nn = 0; nn < 16; nn++) {
            float4 a  = *(const float4*)&As[nn * 68 + ty * 4];
            float4 b0 = *(const float4*)&Cs[nn * 132 + tx * 4];
            float4 b1 = *(const float4*)&Cs[nn * 132 + 64 + tx * 4];
            float av[4] = {a.x, a.y, a.z, a.w};
            float bv[8] = {b0.x, b0.y, b0.z, b0.w, b1.x, b1.y, b1.z, b1.w};
            #pragma unroll
            for (int u = 0; u < 4; u++)
                #pragma unroll
                for (int v = 0; v < 8; v++) acc[u][v] += av[u] * bv[v];
        }
        __syncthreads();
    }
    #pragma unroll
    for (int u = 0; u < 4; u++) {
        int k = k0 + ty * 4 + u;
        float* dst = &g_CBT[(sj * CH + k) * CH + i0];
        *(float4*)&dst[tx * 4]      = make_float4(acc[u][0], acc[u][1], acc[u][2], acc[u][3]);
        *(float4*)&dst[64 + tx * 4] = make_float4(acc[u][4], acc[u][5], acc[u][6], acc[u][7]);
    }
}

// ---------------- kernel 3: chunk states (tf32 mma) -------------------------
// states[n,p] = sum_k (cd*ekd[k]) * B[k,n] * x[k,h,p]
// grid: (2, S_*NC*H_); block 256; CTA = 128(n) x 128(p), K=256
__global__ __launch_bounds__(256) void k_states(const float* __restrict__ x,
                                                const float* __restrict__ BC)
{
    int by = blockIdx.y;                 // sjh
    int s = by >> 8, j = (by >> 4) & 15, h = by & 15;
    int n0 = blockIdx.x * 128;
    bool fwd = (s < B_);
    int bb = fwd ? s : s - B_;
    int tid = threadIdx.x;
    int lane = tid & 31, w = tid >> 5;
    int wr = w & 3, wc = w >> 2;
    float cdv = g_cd[by];
    int ekb = by * CH;

    __shared__ __align__(16) float As[16 * PITCH];   // [k][n] weighted B (tf32)
    __shared__ __align__(16) float Bs[16 * PITCH];   // [k][p] x          (tf32)

    float acc[2][8][4];
    #pragma unroll
    for (int mt = 0; mt < 2; mt++)
        #pragma unroll
        for (int nt = 0; nt < 8; nt++)
            #pragma unroll
            for (int q = 0; q < 4; q++) acc[mt][nt][q] = 0.f;

    for (int k0 = 0; k0 < CH; k0 += 16) {
        #pragma unroll
        for (int r = 0; r < 8; r++) {
            int e = tid + r * 256;
            int kq = e >> 7, nn = e & 127;
            int t = j * CH + k0 + kq;
            int tg = fwd ? t : (L_ - 1 - t);
            float wgt = cdv * g_ekd[ekb + k0 + kq];
            As[kq * PITCH + nn] = f2tf(BC[(bb * L_ + tg) * (2 * NSTATE) + n0 + nn] * wgt);
        }
        #pragma unroll
        for (int r = 0; r < 8; r++) {
            int e = tid + r * 256;
            int kq = e >> 7, pp = e & 127;
            int t = j * CH + k0 + kq;
            int tg = fwd ? t : (L_ - 1 - t);
            Bs[kq * PITCH + pp] = f2tf(x[(bb * L_ + tg) * DIN + h * P_ + pp]);
        }
        __syncthreads();
        mma_step16(As, Bs, acc, wr, wc, lane);
        __syncthreads();
    }

    int g = lane >> 2, tig = lane & 3;
    #pragma unroll
    for (int mt = 0; mt < 2; mt++) {
        int n = n0 + wr * 32 + mt * 16 + g;
        #pragma unroll
        for (int nt = 0; nt < 8; nt++) {
            int pc = wc * 64 + nt * 8 + 2 * tig;
            float* base = &g_states[((size_t)(by * NSTATE + n)) * P_ + pc];
            *(float2*)base            = make_float2(acc[mt][nt][0], acc[mt][nt][1]);
            *(float2*)(base + 8 * P_) = make_float2(acc[mt][nt][2], acc[mt][nt][3]);
        }
    }
}

// ---------------- kernel 3b: inter-chunk recurrence (MLP-batched) ----------
// Each thread owns one (s,h,n,p4); loads all 16 chunk values first (MLP=16).
__global__ void k_scan()
{
    int tid = blockIdx.x * 256 + threadIdx.x;   // 0 .. 524287
    int q  = tid & 31;                          // p/4
    int nv = (tid >> 5) & 255;
    int hh = (tid >> 13) & 15;
    int s  = tid >> 17;

    float4 v[NC];
    float  d[NC];
    #pragma unroll
    for (int j = 0; j < NC; j++) {
        int sjh = (s * 16 + j) * 16 + hh;
        v[j] = *(const float4*)&g_states[((size_t)(sjh * NSTATE + nv)) * P_ + q * 4];
        d[j] = g_cd[sjh];
    }
    float4 c = make_float4(0.f, 0.f, 0.f, 0.f);
    #pragma unroll
    for (int j = 0; j < NC; j++) {
        int sjh = (s * 16 + j) * 16 + hh;
        *(float4*)&g_states[((size_t)(sjh * NSTATE + nv)) * P_ + q * 4] = c;
        float dd = d[j];
        c.x = c.x * dd + v[j].x;
        c.y = c.y * dd + v[j].y;
        c.z = c.z * dd + v[j].z;
        c.w = c.w * dd + v[j].w;
    }
}

// ---------------- kernel 4: y = [G | ei*C] @ [X ; prev] (tf32 mma) ----------
// G[i,k] = CBT[k][i]*ei[i]*ekd[k]*(k<=i); grid (2, S_*NC*H_); 128x128 per CTA
__global__ __launch_bounds__(256) void k_y(const float* __restrict__ x,
                                           const float* __restrict__ BC)
{
    int by = blockIdx.y;                 // sjh
    int s = by >> 8, j = (by >> 4) & 15, h = by & 15;
    int sj = by >> 4;
    int i0 = blockIdx.x * 128;
    bool fwd = (s < B_);
    int bb = fwd ? s : s - B_;
    int tid = threadIdx.x;
    int lane = tid & 31, w = tid >> 5;
    int wr = w & 3, wc = w >> 2;
    int base = by * CH;

    __shared__ __align__(16) float As[16 * PITCH];
    __shared__ __align__(16) float Bs[16 * PITCH];
    __shared__ float eis[128];
    if (tid < 128) eis[tid] = g_ei[base + i0 + tid];
    __syncthreads();

    float acc[2][8][4];
    #pragma unroll
    for (int mt = 0; mt < 2; mt++)
        #pragma unroll
        for (int nt = 0; nt < 8; nt++)
            #pragma unroll
            for (int q = 0; q < 4; q++) acc[mt][nt][q] = 0.f;

    int ntri = (i0 == 0) ? 8 : 16;       // skip fully-masked triangular tiles
    for (int kt = 0; kt < ntri + 16; ++kt) {
        bool first = (kt < ntri);
        int k0 = first ? kt * 16 : (kt - ntri) * 16;
        if (first) {
            #pragma unroll
            for (int r = 0; r < 8; r++) {
                int e = tid + r * 256;
                int kk = e >> 7, ii = e & 127;
                int kg = k0 + kk, ig = i0 + ii;
                float v = g_CBT[(sj * CH + kg) * CH + ig] * eis[ii] * g_ekd[base + kg];
                As[kk * PITCH + ii] = (kg <= ig) ? f2tf(v) : 0.f;
            }
            #pragma unroll
            for (int r = 0; r < 8; r++) {
                int e = tid + r * 256;
                int kk = e >> 7, pp = e & 127;
                int t = j * CH + k0 + kk;
                int tg = fwd ? t : (L_ - 1 - t);
                Bs[kk * PITCH + pp] = f2tf(x[(bb * L_ + tg) * DIN + h * P_ + pp]);
            }
        } else {
            #pragma unroll
            for (int r = 0; r < 8; r++) {
                int e = tid + r * 256;
                int ii = e >> 4, nl = e & 15;
                int ig = i0 + ii;
                int t = j * CH + ig;
                int tg = fwd ? t : (L_ - 1 - t);
                As[nl * PITCH + ii] =
                    f2tf(BC[(bb * L_ + tg) * (2 * NSTATE) + NSTATE + k0 + nl] * eis[ii]);
            }
            #pragma unroll
            for (int r = 0; r < 8; r++) {
                int e = tid + r * 256;
                int kk = e >> 7, pp = e & 127;
                Bs[kk * PITCH + pp] = f2tf(g_states[((size_t)(by * NSTATE + k0 + kk)) * P_ + pp]);
            }
        }
        __syncthreads();
        mma_step16(As, Bs, acc, wr, wc, lane);
        __syncthreads();
    }

    int g = lane >> 2, tig = lane & 3;
    #pragma unroll
    for (int mt = 0; mt < 2; mt++) {
        int irow = i0 + wr * 32 + mt * 16 + g;
        int t = j * CH + irow;
        #pragma unroll
        for (int nt = 0; nt < 8; nt++) {
            int pc = wc * 64 + nt * 8 + 2 * tig;
            float* dst = &g_ysc[((size_t)(s * L_ + t)) * DIN + h * P_ + pc];
            *(float2*)dst             = make_float2(acc[mt][nt][0], acc[mt][nt][1]);
            *(float2*)(dst + 8 * DIN) = make_float2(acc[mt][nt][2], acc[mt][nt][3]);
        }
    }
}

// ---------------- kernel 5: gate + roll + flip fusion ----------------------
__global__ void k_fuse(const float* __restrict__ x, const float* __restrict__ W,
                       const float* __restrict__ D, float* __restrict__ out)
{
    int bt = blockIdx.x;
    int bb = bt / L_, t = bt % L_;
    __shared__ __align__(16) float xs[DIN];
    __shared__ float gate[H_];
    int tid = threadIdx.x;
    const float* xrow = x + (size_t)bt * DIN;
    #pragma unroll
    for (int r = 0; r < 2; r++) {
        int i4 = tid + r * 256;
        ((float4*)xs)[i4] = ((const float4*)xrow)[i4];
    }
    __syncthreads();

    int w = tid >> 5, lane = tid & 31;
    #pragma unroll
    for (int hh = w; hh < H_; hh += 8) {
        float g = 0.f;
        const float4* Wr = (const float4*)(W + hh * DIN);
        #pragma unroll
        for (int d4 = lane; d4 < DIN / 4; d4 += 32) {
            float4 xv = ((float4*)xs)[d4];
            float4 wv = Wr[d4];
            g += xv.x * wv.x + xv.y * wv.y + xv.z * wv.z + xv.w * wv.w;
        }
        #pragma unroll
        for (int off = 16; off; off >>= 1) g += __shfl_down_sync(0xffffffffu, g, off);
        if (lane == 0) gate[hh] = g + D[hh];
    }
    __syncthreads();

    const float4* yfw = (t > 0)
        ? (const float4*)(g_ysc + ((size_t)bb * L_ + (t - 1)) * DIN) : (const float4*)0;
    const float4* ybw = (t < L_ - 1)
        ? (const float4*)(g_ysc + ((size_t)(B_ + bb) * L_ + (L_ - 2 - t)) * DIN) : (const float4*)0;
    float4* o = (float4*)(out + (size_t)bt * DIN);
    #pragma unroll
    for (int r = 0; r < 2; r++) {
        int i4 = tid + r * 256;
        float4 xv = ((float4*)xs)[i4];
        float gh = gate[i4 >> 5];
        float4 a = yfw ? yfw[i4] : make_float4(0.f, 0.f, 0.f, 0.f);
        float4 b = ybw ? ybw[i4] : make_float4(0.f, 0.f, 0.f, 0.f);
        float4 res;
        res.x = a.x + b.x + xv.x * gh;
        res.y = a.y + b.y + xv.y * gh;
        res.z = a.z + b.z + xv.z * gh;
        res.w = a.w + b.w + xv.w * gh;
        o[i4] = res;
    }
}

// ---------------- launcher --------------------------------------------------
extern "C" void kernel_launch(void* const* d_in, const int* in_sizes, int n_in,
                              void* d_out, int out_size)
{
    (void)in_sizes; (void)n_in; (void)out_size;
    const float* x     = (const float*)d_in[0];
    const float* BC    = (const float*)d_in[1];
    const float* dt    = (const float*)d_in[2];
    const float* A_log = (const float*)d_in[3];
    const float* D     = (const float*)d_in[4];
    const float* W     = (const float*)d_in[5];
    float* out = (float*)d_out;

    k_prep  <<<S_ * NC, 512>>>(dt, A_log);
    k_cb    <<<dim3(8, S_ * NC), 256>>>(BC);
    k_states<<<dim3(2, S_ * NC * H_), 256>>>(x, BC);
    k_scan  <<<(S_ * H_ * NSTATE * P_ / 4) / 256, 256>>>();
    k_y     <<<dim3(2, S_ * NC * H_), 256>>>(x, BC);
    k_fuse  <<<B_ * L_, 256>>>(x, W, D, out);
}